// round 12
// baseline (speedup 1.0000x reference)
#include <cuda_runtime.h>
#include <cuda_fp16.h>
#include <cstdint>

// Problem constants (fixed by the dataset)
#define NN   50000
#define EI   400000          // raw edges
#define EEv  450000          // edges + self loops
#define HC   256             // H*C (layer-1 width) == IN
#define OUTD 16
#define NEG  0.2f
#define NB1  49              // ceil(NN/1024)
#define NA   25088           // node-split point (196 * 128)

// ---------------- scratch (static device globals; no allocs) ----------------
__device__ __half2 g_xl1h[NN * 128];   // xl1 in fp16 (gathered 9x per node in agg1)
__device__ float g_xr1[NN * HC];
__device__ float g_h  [NN * HC];       // stored tf32-rounded (A operand of gemm2)
__device__ float g_xl2[NN * OUTD];
__device__ float g_xr2[NN * OUTD];
__device__ __half g_w1h[2 * HC * HC];  // [z][n][k] = fp16(W_z[k][n])  (transposed)
__device__ float g_w2t [HC * 32];      // [Wl2|Wr2] concat, tf32 bits
__device__ int   g_deg [NN];           // zero at start of every call
__device__ int   g_ex  [NN];
__device__ int   g_off [NN + 1];
__device__ int   g_cur [NN];
__device__ int   g_csrc[EEv];
__device__ int   g_bsum[64];

// ---------------- mma helpers ----------------
__device__ __forceinline__ uint32_t f2tf(float f) {
    uint32_t u;
    asm("cvt.rna.tf32.f32 %0, %1;" : "=r"(u) : "f"(f));
    return u;
}

// tf32 m16n8k8 (kept for gemm2)
__device__ __forceinline__ void mma8(float* c, const uint32_t* a, const uint32_t* b) {
    asm volatile(
        "mma.sync.aligned.m16n8k8.row.col.f32.tf32.tf32.f32 "
        "{%0,%1,%2,%3},{%4,%5,%6,%7},{%8,%9},{%0,%1,%2,%3};\n"
        : "+f"(c[0]), "+f"(c[1]), "+f"(c[2]), "+f"(c[3])
        : "r"(a[0]), "r"(a[1]), "r"(a[2]), "r"(a[3]), "r"(b[0]), "r"(b[1]));
}

// fp16 m16n8k16, fp32 accumulate (gemm1)
__device__ __forceinline__ void mma16(float* c, const uint32_t* a, const uint32_t* b) {
    asm volatile(
        "mma.sync.aligned.m16n8k16.row.col.f32.f16.f16.f32 "
        "{%0,%1,%2,%3},{%4,%5,%6,%7},{%8,%9},{%0,%1,%2,%3};\n"
        : "+f"(c[0]), "+f"(c[1]), "+f"(c[2]), "+f"(c[3])
        : "r"(a[0]), "r"(a[1]), "r"(a[2]), "r"(a[3]), "r"(b[0]), "r"(b[1]));
}

__device__ __forceinline__ void ldm4(uint32_t* r, uint32_t addr) {
    asm volatile("ldmatrix.sync.aligned.m8n8.x4.shared.b16 {%0,%1,%2,%3}, [%4];"
        : "=r"(r[0]), "=r"(r[1]), "=r"(r[2]), "=r"(r[3]) : "r"(addr));
}

__device__ __forceinline__ void cp16(uint32_t dst, const void* src, int sz) {
    asm volatile("cp.async.cg.shared.global [%0], [%1], 16, %2;\n"
                 :: "r"(dst), "l"(src), "r"(sz));
}
__device__ __forceinline__ void cpcommit() { asm volatile("cp.async.commit_group;\n" ::: "memory"); }
__device__ __forceinline__ void cpwait0()  { asm volatile("cp.async.wait_group 0;\n" ::: "memory"); }

__device__ __forceinline__ uint32_t smem_u32(const void* p) {
    uint32_t a;
    asm("{ .reg .u64 t; cvta.to.shared.u64 t, %1; cvt.u32.u64 %0, t; }" : "=r"(a) : "l"(p));
    return a;
}

// ---------------- weight preprocessing (main stream, feeds gemm1/gemm2) -----
__global__ void k_wconv(const float* __restrict__ Wl1, const float* __restrict__ Wr1,
                        const float* __restrict__ Wl2, const float* __restrict__ Wr2) {
    int e = blockIdx.x * 256 + threadIdx.x;
    if (e < 2 * HC * HC) {      // transpose+convert layer-1 weights: g_w1h[z][n][k]
        int z = e >> 16, idx = e & 65535;
        int n = idx >> 8, k = idx & 255;
        const float* Wz = z ? Wr1 : Wl1;
        g_w1h[z * 65536 + n * 256 + k] = __float2half(Wz[k * 256 + n]);
    }
    if (e < HC * OUTD) {
        int r = e >> 4, c = e & 15;
        g_w2t[r * 32 + c]      = __uint_as_float(f2tf(Wl2[e]));
        g_w2t[r * 32 + 16 + c] = __uint_as_float(f2tf(Wr2[e]));
    }
}

// ---------------- CSR build (side stream) -----------------------------------
__global__ void k_hist(const int* __restrict__ ei) {
    int e = blockIdx.x * 256 + threadIdx.x;
    if (e >= EEv) return;
    int d = (e < EI) ? ei[EI + e] : (e - EI);
    atomicAdd(&g_deg[d], 1);
}

__global__ void k_scan1() {
    int i = blockIdx.x * 1024 + threadIdx.x;
    int v = (i < NN) ? g_deg[i] : 0;
    int x = v;
    #pragma unroll
    for (int o = 1; o < 32; o <<= 1) {
        int y = __shfl_up_sync(0xffffffffu, x, o);
        if ((threadIdx.x & 31) >= o) x += y;
    }
    __shared__ int ws[32];
    if ((threadIdx.x & 31) == 31) ws[threadIdx.x >> 5] = x;
    __syncthreads();
    if (threadIdx.x < 32) {
        int s = ws[threadIdx.x];
        #pragma unroll
        for (int o = 1; o < 32; o <<= 1) {
            int y = __shfl_up_sync(0xffffffffu, s, o);
            if (threadIdx.x >= (unsigned)o) s += y;
        }
        ws[threadIdx.x] = s;
    }
    __syncthreads();
    int incl = x + ((threadIdx.x >= 32) ? ws[(threadIdx.x >> 5) - 1] : 0);
    if (i < NN) g_ex[i] = incl - v;
    if (threadIdx.x == 1023) g_bsum[blockIdx.x] = incl;
}

__global__ void k_off() {
    __shared__ int s_pre[2];
    int t = threadIdx.x;
    int gb = blockIdx.x >> 2;
    if (t < 64) {
        int v = (t < gb && t < NB1) ? g_bsum[t] : 0;
        #pragma unroll
        for (int o = 16; o >= 1; o >>= 1) v += __shfl_xor_sync(0xffffffffu, v, o);
        if ((t & 31) == 0) s_pre[t >> 5] = v;
    }
    __syncthreads();
    int pre = s_pre[0] + s_pre[1];
    int i = blockIdx.x * 256 + t;
    if (i < NN) {
        int o = g_ex[i] + pre;
        g_off[i] = o;
        g_cur[i] = o;
    }
    if (i == 0) g_off[NN] = EEv;
}

__global__ void k_scatter(const int* __restrict__ ei) {
    int e = blockIdx.x * 256 + threadIdx.x;
    if (e < NN) g_deg[e] = 0;
    if (e >= EEv) return;
    int s = (e < EI) ? ei[e]      : (e - EI);
    int d = (e < EI) ? ei[EI + e] : (e - EI);
    int p = atomicAdd(&g_cur[d], 1);
    g_csrc[p] = s;
}

// ---------------- layer-1 GEMM: fp16 HMMA m16n8k16 + ldmatrix ---------------
#define AH 40
#define BH 40
#define ASTG (128 * AH)     // fp16 per A stage
#define BSTG (128 * BH)     // fp16 per B stage
__global__ __launch_bounds__(256, 2) void k_gemm1h(
    const float* __restrict__ X,
    const float* __restrict__ b0, const float* __restrict__ b1)
{
    extern __shared__ __half smh[];
    __half* As = smh;                // [2][ASTG]
    __half* Bs = smh + 2 * ASTG;     // [2][BSTG]

    const __half* W   = g_w1h + (size_t)blockIdx.z * 65536;
    const float* bias = blockIdx.z ? b1 : b0;

    int m0 = blockIdx.x * 128;
    int n0 = blockIdx.y * 128;
    int t = threadIdx.x;
    int warp = t >> 5, lane = t & 31;
    int wm = warp & 3, wn = warp >> 2;
    int r = lane >> 2, cq = lane & 3;

    uint32_t aS = smem_u32(As);
    uint32_t bS = smem_u32(Bs);

    int arow_lm = lane & 15;
    int akoff   = (lane >> 4) * 8;
    int nrow_lm = (lane & 7) + ((lane >> 4) << 3);
    int bkoff   = lane & 8;

    float c[2][8][4];
    #pragma unroll
    for (int mt = 0; mt < 2; mt++)
        #pragma unroll
        for (int nt = 0; nt < 8; nt++)
            #pragma unroll
            for (int q = 0; q < 4; q++) c[mt][nt][q] = 0.f;

    int arow = t >> 1, ahalf = t & 1;
    const float* aptr = X + (size_t)(m0 + arow) * 256 + ahalf * 16;
    bool aok = (m0 + arow) < NN;
    float4 va[4];
    auto ldgA = [&](int kb) {
        #pragma unroll
        for (int j = 0; j < 4; j++)
            va[j] = aok ? *(const float4*)(aptr + kb + j * 4)
                        : make_float4(0.f, 0.f, 0.f, 0.f);
    };
    auto stsA = [&](int s) {
        uint32_t h[8];
        #pragma unroll
        for (int j = 0; j < 4; j++) {
            __half2 lo = __floats2half2_rn(va[j].x, va[j].y);
            __half2 hi = __floats2half2_rn(va[j].z, va[j].w);
            h[2 * j]     = *(uint32_t*)&lo;
            h[2 * j + 1] = *(uint32_t*)&hi;
        }
        uint32_t dst = aS + (uint32_t)(s * ASTG + arow * AH + ahalf * 16) * 2u;
        asm volatile("st.shared.v4.b32 [%0], {%1,%2,%3,%4};"
                     :: "r"(dst), "r"(h[0]), "r"(h[1]), "r"(h[2]), "r"(h[3]) : "memory");
        asm volatile("st.shared.v4.b32 [%0], {%1,%2,%3,%4};"
                     :: "r"(dst + 16), "r"(h[4]), "r"(h[5]), "r"(h[6]), "r"(h[7]) : "memory");
    };
    auto cpB = [&](int s, int kb) {
        #pragma unroll
        for (int j = 0; j < 2; j++) {
            int g   = t + j * 256;
            int row = g >> 2, q = g & 3;
            uint32_t dst = bS + (uint32_t)(s * BSTG + row * BH + q * 8) * 2u;
            cp16(dst, W + (size_t)(n0 + row) * 256 + kb + q * 8, 16);
        }
    };

    cpB(0, 0); cpcommit();
    ldgA(0);

    #pragma unroll 1
    for (int i = 0; i < 8; i++) {
        int s = i & 1;
        stsA(s);
        cpwait0();
        __syncthreads();
        if (i < 7) { cpB(1 - s, (i + 1) * 32); cpcommit(); ldgA((i + 1) * 32); }

        uint32_t aBase = aS + (uint32_t)(s * ASTG) * 2u;
        uint32_t bBase = bS + (uint32_t)(s * BSTG) * 2u;
        #pragma unroll
        for (int ks = 0; ks < 2; ks++) {
            int k = ks * 16;
            uint32_t a[2][4], b[8][2];
            #pragma unroll
            for (int mt = 0; mt < 2; mt++) {
                uint32_t ad = aBase +
                    (uint32_t)((wm * 32 + mt * 16 + arow_lm) * AH + k + akoff) * 2u;
                ldm4(a[mt], ad);
            }
            #pragma unroll
            for (int ntp = 0; ntp < 4; ntp++) {
                uint32_t bd = bBase +
                    (uint32_t)((wn * 64 + ntp * 16 + nrow_lm) * BH + k + bkoff) * 2u;
                ldm4(&b[2 * ntp][0], bd);
            }
            #pragma unroll
            for (int mt = 0; mt < 2; mt++)
                #pragma unroll
                for (int nt = 0; nt < 8; nt++)
                    mma16(c[mt][nt], a[mt], b[nt]);
        }
        if (i < 7) __syncthreads();
    }

    // epilogue: + bias; xl -> fp16, xr -> fp32
    if (blockIdx.z == 0) {
        #pragma unroll
        for (int mt = 0; mt < 2; mt++) {
            #pragma unroll
            for (int nt = 0; nt < 8; nt++) {
                int gr = m0 + wm * 32 + mt * 16 + r;
                int gc = n0 + wn * 64 + nt * 8 + cq * 2;
                float bv0 = bias[gc], bv1 = bias[gc + 1];
                if (gr < NN)
                    g_xl1h[(size_t)gr * 128 + (gc >> 1)] =
                        __floats2half2_rn(c[mt][nt][0] + bv0, c[mt][nt][1] + bv1);
                if (gr + 8 < NN)
                    g_xl1h[(size_t)(gr + 8) * 128 + (gc >> 1)] =
                        __floats2half2_rn(c[mt][nt][2] + bv0, c[mt][nt][3] + bv1);
            }
        }
    } else {
        #pragma unroll
        for (int mt = 0; mt < 2; mt++) {
            #pragma unroll
            for (int nt = 0; nt < 8; nt++) {
                int gr = m0 + wm * 32 + mt * 16 + r;
                int gc = n0 + wn * 64 + nt * 8 + cq * 2;
                float bv0 = bias[gc], bv1 = bias[gc + 1];
                if (gr < NN) {
                    float2 v; v.x = c[mt][nt][0] + bv0; v.y = c[mt][nt][1] + bv1;
                    *(float2*)&g_xr1[(size_t)gr * HC + gc] = v;
                }
                if (gr + 8 < NN) {
                    float2 v; v.x = c[mt][nt][2] + bv0; v.y = c[mt][nt][3] + bv1;
                    *(float2*)&g_xr1[(size_t)(gr + 8) * HC + gc] = v;
                }
            }
        }
    }
}

// ---------------- layer-1 attention: paired softmax, 4-edge lookahead --------
// warp per dst node in [nbase, nbase+ncnt); lane owns 8 channels.
__global__ __launch_bounds__(256) void k_agg1(const float* __restrict__ att,
                                              const float* __restrict__ b1,
                                              int nbase, int ncnt)
{
    int gw   = ((blockIdx.x * 256 + threadIdx.x) >> 5);
    int lane = threadIdx.x & 31;
    if (gw >= ncnt) return;
    gw += nbase;
    int c0 = lane * 8;
    size_t lo = (size_t)lane * 4;

    const float4* xrp = (const float4*)&g_xr1[(size_t)gw * HC + c0];
    float4 xr0 = xrp[0], xr1 = xrp[1];
    const float4* ap = (const float4*)&att[c0];
    float4 at0 = ap[0], at1 = ap[1];

    float acc[8];
    #pragma unroll
    for (int q = 0; q < 8; q++) acc[q] = 0.f;
    float den = 0.f, mx = -1e30f;

    int off = g_off[gw], dg = g_off[gw + 1] - off;

    auto score = [&](const uint4& raw, float* f) -> float {
        const __half2* hp = (const __half2*)&raw;
        float2 a0 = __half22float2(hp[0]);
        float2 a1 = __half22float2(hp[1]);
        float2 a2 = __half22float2(hp[2]);
        float2 a3 = __half22float2(hp[3]);
        f[0] = a0.x; f[1] = a0.y; f[2] = a1.x; f[3] = a1.y;
        f[4] = a2.x; f[5] = a2.y; f[6] = a3.x; f[7] = a3.y;
        float m, l, p;
        m = a0.x + xr0.x; l = (m > 0.f) ? m : NEG * m; p  = l * at0.x;
        m = a0.y + xr0.y; l = (m > 0.f) ? m : NEG * m; p += l * at0.y;
        m = a1.x + xr0.z; l = (m > 0.f) ? m : NEG * m; p += l * at0.z;
        m = a1.y + xr0.w; l = (m > 0.f) ? m : NEG * m; p += l * at0.w;
        m = a2.x + xr1.x; l = (m > 0.f) ? m : NEG * m; p += l * at1.x;
        m = a2.y + xr1.y; l = (m > 0.f) ? m : NEG * m; p += l * at1.y;
        m = a3.x + xr1.z; l = (m > 0.f) ? m : NEG * m; p += l * at1.z;
        m = a3.y + xr1.w; l = (m > 0.f) ? m : NEG * m; p += l * at1.w;
        return p;
    };
    auto eload = [&](int k) -> uint4 {     // clamped edge load
        int s = g_csrc[off + min(k, dg - 1)];
        return *(const uint4*)&g_xl1h[(size_t)s * 128 + lo];
    };

    // 2-pair (4-edge) lookahead ring
    uint4 rA0 = eload(0), rB0 = eload(1);
    uint4 rA1 = eload(2), rB1 = eload(3);

    int i = 0;
    for (; i + 1 < dg; i += 2) {
        uint4 c0v = rA0, c1v = rB0;
        rA0 = rA1; rB0 = rB1;
        rA1 = eload(i + 4);
        rB1 = eload(i + 5);

        float f0[8], f1[8];
        float p0 = score(c0v, f0);
        float p1 = score(c1v, f1);
        p0 += __shfl_xor_sync(0xffffffffu, p0, 1);
        p1 += __shfl_xor_sync(0xffffffffu, p1, 1);
        p0 += __shfl_xor_sync(0xffffffffu, p0, 2);
        p1 += __shfl_xor_sync(0xffffffffu, p1, 2);
        p0 += __shfl_xor_sync(0xffffffffu, p0, 4);
        p1 += __shfl_xor_sync(0xffffffffu, p1, 4);

        float mn   = fmaxf(mx, fmaxf(p0, p1));
        float corr = __expf(mx - mn);
        float w0   = __expf(p0 - mn);
        float w1   = __expf(p1 - mn);
        mx  = mn;
        den = den * corr + w0 + w1;
        #pragma unroll
        for (int q = 0; q < 8; q++)
            acc[q] = acc[q] * corr + w0 * f0[q] + w1 * f1[q];
    }
    if (i < dg) {   // odd remainder: edge dg-1 sits in rA0 after the shifts
        float f0[8];
        float p0 = score(rA0, f0);
        p0 += __shfl_xor_sync(0xffffffffu, p0, 1);
        p0 += __shfl_xor_sync(0xffffffffu, p0, 2);
        p0 += __shfl_xor_sync(0xffffffffu, p0, 4);
        float mn   = fmaxf(mx, p0);
        float corr = __expf(mx - mn);
        float w0   = __expf(p0 - mn);
        mx  = mn;
        den = den * corr + w0;
        #pragma unroll
        for (int q = 0; q < 8; q++)
            acc[q] = acc[q] * corr + w0 * f0[q];
    }

    float inv = 1.f / (den + 1e-16f);
    float4 o0, o1;
    o0.x = __uint_as_float(f2tf(tanhf(acc[0] * inv + b1[c0 + 0])));
    o0.y = __uint_as_float(f2tf(tanhf(acc[1] * inv + b1[c0 + 1])));
    o0.z = __uint_as_float(f2tf(tanhf(acc[2] * inv + b1[c0 + 2])));
    o0.w = __uint_as_float(f2tf(tanhf(acc[3] * inv + b1[c0 + 3])));
    o1.x = __uint_as_float(f2tf(tanhf(acc[4] * inv + b1[c0 + 4])));
    o1.y = __uint_as_float(f2tf(tanhf(acc[5] * inv + b1[c0 + 5])));
    o1.z = __uint_as_float(f2tf(tanhf(acc[6] * inv + b1[c0 + 6])));
    o1.w = __uint_as_float(f2tf(tanhf(acc[7] * inv + b1[c0 + 7])));
    float4* hpo = (float4*)&g_h[(size_t)gw * HC + c0];
    hpo[0] = o0; hpo[1] = o1;
}

// ---------------- layer-2 GEMM (tf32 HMMA): [xl2|xr2] = h @ [Wl2|Wr2] + b ----
#define AP2 36
#define BP2 40
__global__ __launch_bounds__(256) void k_gemm2(
    const float* __restrict__ bl2, const float* __restrict__ br2, int mbase)
{
    extern __shared__ float smemf[];
    float* As = smemf;                  // [2][128*AP2]
    float* Bs = smemf + 2 * 128 * AP2;  // [256*BP2]
    float* bs = Bs + 256 * BP2;         // [32]

    int m0 = mbase + blockIdx.x * 128;
    int t = threadIdx.x;
    int warp = t >> 5, lane = t & 31;
    int ar = lane >> 2, ac = lane & 3;

    #pragma unroll
    for (int i = 0; i < 8; i++) {
        int lin = t + i * 256;
        int r   = lin >> 3;
        int c4  = (lin & 7) * 4;
        float4 v = *(const float4*)&g_w2t[r * 32 + c4];
        float* d = Bs + r * BP2 + c4;
        d[0] = v.x; d[1] = v.y; d[2] = v.z; d[3] = v.w;
    }
    if (t < 32) bs[t] = (t < 16) ? bl2[t] : br2[t - 16];

    uint32_t aS = (uint32_t)__cvta_generic_to_shared(As);

    float c[4][4];
    #pragma unroll
    for (int nt = 0; nt < 4; nt++)
        #pragma unroll
        for (int q = 0; q < 4; q++) c[nt][q] = 0.f;

    auto load_stage = [&](int s, int kb) {
        uint32_t ab = aS + (uint32_t)(s * 128 * AP2) * 4u;
        #pragma unroll
        for (int i = 0; i < 4; i++) {
            int r  = (t >> 3) + i * 32;
            int c4 = (t & 7) * 4;
            int gr = m0 + r;
            const float* src = g_h + (size_t)gr * 256 + kb + c4;
            cp16(ab + (uint32_t)(r * AP2 + c4) * 4u, src, (gr < NN) ? 16 : 0);
        }
    };

    load_stage(0, 0);
    cpcommit();

    for (int i = 0; i < 8; i++) {
        cpwait0();
        __syncthreads();
        if (i + 1 < 8) { load_stage((i + 1) & 1, (i + 1) * 32); cpcommit(); }

        const uint32_t* Ac = (const uint32_t*)(As + (i & 1) * 128 * AP2);
        const uint32_t* Bu = (const uint32_t*)Bs;
        int kb = i * 32;
        #pragma unroll
        for (int ks = 0; ks < 4; ks++) {
            int k = ks * 8;
            uint32_t a[4], b[4][2];
            int m = warp * 16;
            a[0] = Ac[(m + ar)     * AP2 + k + ac];
            a[1] = Ac[(m + ar + 8) * AP2 + k + ac];
            a[2] = Ac[(m + ar)     * AP2 + k + ac + 4];
            a[3] = Ac[(m + ar + 8) * AP2 + k + ac + 4];
            #pragma unroll
            for (int nt = 0; nt < 4; nt++) {
                int n = nt * 8 + ar;
                b[nt][0] = Bu[(kb + k + ac)     * BP2 + n];
                b[nt][1] = Bu[(kb + k + ac + 4) * BP2 + n];
            }
            #pragma unroll
            for (int nt = 0; nt < 4; nt++)
                mma8(c[nt], a, b[nt]);
        }
        __syncthreads();
    }

    #pragma unroll
    for (int nt = 0; nt < 4; nt++) {
        int gr = m0 + warp * 16 + ar;
        int gc = nt * 8 + ac * 2;
        float bv0 = bs[gc], bv1 = bs[gc + 1];
        float* base = (gc < 16) ? g_xl2 : g_xr2;
        int col = (gc < 16) ? gc : gc - 16;
        if (gr < NN) {
            float2 v; v.x = c[nt][0] + bv0; v.y = c[nt][1] + bv1;
            *(float2*)&base[(size_t)gr * OUTD + col] = v;
        }
        if (gr + 8 < NN) {
            float2 v; v.x = c[nt][2] + bv0; v.y = c[nt][3] + bv1;
            *(float2*)&base[(size_t)(gr + 8) * OUTD + col] = v;
        }
    }
}

// ---------------- layer-2 aggregation (2 nodes/warp, 2-edge-paired) ---------
__global__ __launch_bounds__(256) void k_agg2(const float* __restrict__ att2,
                                              const float* __restrict__ b2,
                                              float* __restrict__ out,
                                              int out_size)
{
    int warpg = (blockIdx.x * 256 + threadIdx.x) >> 5;
    int lane  = threadIdx.x & 31;
    int half  = lane >> 4;
    int j     = lane & 15;
    int node  = warpg * 2 + half;
    bool ok   = node < NN;
    if (warpg * 2 >= NN) return;

    float xr = ok ? g_xr2[(size_t)node * OUTD + j] : 0.f;
    float at = att2[j];
    float acc = 0.f, den = 0.f, mx = -1e30f;

    int off = ok ? g_off[node] : 0;
    int dg  = ok ? (g_off[node + 1] - off) : 0;
    int dmax = __reduce_max_sync(0xffffffffu, dg);

    for (int i = 0; i < dmax; i += 2) {
        int i0 = (dg > 0) ? min(i,     dg - 1) : 0;
        int i1 = (dg > 0) ? min(i + 1, dg - 1) : 0;
        int s0 = g_csrc[off + i0];
        int s1 = g_csrc[off + i1];
        float v0 = g_xl2[(size_t)s0 * OUTD + j];
        float v1 = g_xl2[(size_t)s1 * OUTD + j];
        float m0v = v0 + xr, m1v = v1 + xr;
        float l0 = (m0v > 0.f) ? m0v : NEG * m0v;
        float l1 = (m1v > 0.f) ? m1v : NEG * m1v;
        float p0 = l0 * at, p1 = l1 * at;
        p0 += __shfl_xor_sync(0xffffffffu, p0, 1);
        p1 += __shfl_xor_sync(0xffffffffu, p1, 1);
        p0 += __shfl_xor_sync(0xffffffffu, p0, 2);
        p1 += __shfl_xor_sync(0xffffffffu, p1, 2);
        p0 += __shfl_xor_sync(0xffffffffu, p0, 4);
        p1 += __shfl_xor_sync(0xffffffffu, p1, 4);
        p0 += __shfl_xor_sync(0xffffffffu, p0, 8);
        p1 += __shfl_xor_sync(0xffffffffu, p1, 8);
        if (i     >= dg) p0 = -1e30f;
        if (i + 1 >= dg) p1 = -1e30f;
        float mn   = fmaxf(mx, fmaxf(p0, p1));
        float corr = __expf(mx - mn);
        float w0   = __expf(p0 - mn);
        float w1   = __expf(p1 - mn);
        mx  = mn;
        den = den * corr + w0 + w1;
        acc = acc * corr + w0 * v0 + w1 * v1;
    }
    float o = acc / (den + 1e-16f) + b2[j];

    float mo = o;
    mo = fmaxf(mo, __shfl_xor_sync(0xffffffffu, mo, 1));
    mo = fmaxf(mo, __shfl_xor_sync(0xffffffffu, mo, 2));
    mo = fmaxf(mo, __shfl_xor_sync(0xffffffffu, mo, 4));
    mo = fmaxf(mo, __shfl_xor_sync(0xffffffffu, mo, 8));
    float ex = __expf(o - mo);
    float se = ex;
    se += __shfl_xor_sync(0xffffffffu, se, 1);
    se += __shfl_xor_sync(0xffffffffu, se, 2);
    se += __shfl_xor_sync(0xffffffffu, se, 4);
    se += __shfl_xor_sync(0xffffffffu, se, 8);
    float ls = o - mo - logf(se);

    if (ok) {
        int i0 = node * OUTD + j;
        if (i0 < out_size) out[i0] = o;
        int i1 = NN * OUTD + node * OUTD + j;
        if (i1 < out_size) out[i1] = ls;
    }
}

// ---------------- launch: forked CSR + split agg1/gemm2 pipeline -------------
extern "C" void kernel_launch(void* const* d_in, const int* in_sizes, int n_in,
                              void* d_out, int out_size)
{
    const float* x     = (const float*)d_in[0];
    const int*   ei    = (const int*)  d_in[1];
    const float* Wl1   = (const float*)d_in[2];
    const float* bl1   = (const float*)d_in[3];
    const float* Wr1   = (const float*)d_in[4];
    const float* br1   = (const float*)d_in[5];
    const float* att1  = (const float*)d_in[6];
    const float* bias1 = (const float*)d_in[7];
    const float* Wl2   = (const float*)d_in[8];
    const float* bl2   = (const float*)d_in[9];
    const float* Wr2   = (const float*)d_in[10];
    const float* br2   = (const float*)d_in[11];
    const float* att2  = (const float*)d_in[12];
    const float* bias2 = (const float*)d_in[13];
    float* out = (float*)d_out;

    const int smem1 = 2 * (ASTG + BSTG) * 2;                 // 40960 B
    const int smem2 = (2 * 128 * AP2 + 256 * BP2 + 32) * 4;  // 77952 B
    cudaFuncSetAttribute(k_gemm1h, cudaFuncAttributeMaxDynamicSharedMemorySize, smem1);
    cudaFuncSetAttribute(k_gemm2, cudaFuncAttributeMaxDynamicSharedMemorySize, smem2);

    // side stream + events (host objects; intentionally not destroyed —
    // destroying a stream holding capture deps can abort capture; kernel_launch
    // runs only a handful of times).
    cudaStream_t s2;
    cudaStreamCreate(&s2);
    cudaEvent_t eFork, eJoin, eA, eB;
    cudaEventCreateWithFlags(&eFork, cudaEventDisableTiming);
    cudaEventCreateWithFlags(&eJoin, cudaEventDisableTiming);
    cudaEventCreateWithFlags(&eA,    cudaEventDisableTiming);
    cudaEventCreateWithFlags(&eB,    cudaEventDisableTiming);

    // fork: CSR build on side stream, GEMM path on main stream
    cudaEventRecord(eFork, 0);
    cudaStreamWaitEvent(s2, eFork, 0);

    k_hist   <<<(EEv + 255) / 256, 256, 0, s2>>>(ei);
    k_scan1  <<<NB1, 1024, 0, s2>>>();
    k_off    <<<(NN + 255) / 256, 256, 0, s2>>>();
    k_scatter<<<(EEv + 255) / 256, 256, 0, s2>>>(ei);
    cudaEventRecord(eJoin, s2);

    k_wconv  <<<512, 256>>>(Wl1, Wr1, Wl2, Wr2);
    dim3 g1((NN + 127) / 128, 2, 2);
    k_gemm1h <<<g1, 256, smem1>>>(x, bl1, br1);

    // agg1 half A on main (needs gemm1h + CSR)
    cudaStreamWaitEvent(0, eJoin, 0);
    k_agg1   <<<(NA * 32 + 255) / 256, 256>>>(att1, bias1, 0, NA);
    cudaEventRecord(eA, 0);

    // agg1 half B on side stream (serialized after half A for pipelining;
    // eA transitively carries gemm1h + CSR deps)
    cudaStreamWaitEvent(s2, eA, 0);
    k_agg1   <<<((NN - NA) * 32 + 255) / 256, 256, 0, s2>>>(att1, bias1, NA, NN - NA);
    cudaEventRecord(eB, s2);

    // gemm2 half A on main overlaps agg1 half B
    k_gemm2  <<<NA / 128, 256, smem2>>>(bl2, br2, 0);

    // gemm2 half B + agg2 after both halves ready
    cudaStreamWaitEvent(0, eB, 0);
    k_gemm2  <<<(NN - NA + 127) / 128, 256, smem2>>>(bl2, br2, NA);
    k_agg2   <<<((NN / 2) * 32 + 255) / 256, 256>>>(att2, bias2, out, out_size);
}

// round 13
// speedup vs baseline: 1.1243x; 1.1243x over previous
#include <cuda_runtime.h>
#include <cuda_fp16.h>
#include <cstdint>

// Problem constants (fixed by the dataset)
#define NN   50000
#define EI   400000          // raw edges
#define EEv  450000          // edges + self loops
#define HC   256             // H*C (layer-1 width) == IN
#define OUTD 16
#define NEG  0.2f
#define NB1  49              // ceil(NN/1024)

// ---------------- scratch (static device globals; no allocs) ----------------
__device__ __half2 g_xl1h[NN * 128];   // xl1 in fp16 (gathered 9x per node in agg1)
__device__ float g_xr1[NN * HC];
__device__ float g_h  [NN * HC];       // stored tf32-rounded (A operand of gemm2)
__device__ float g_xl2[NN * OUTD];
__device__ float g_xr2[NN * OUTD];
__device__ __half g_w1h[2 * HC * HC];  // [z][n][k] = fp16(W_z[k][n])  (transposed)
__device__ float g_w2t [HC * 32];      // [Wl2|Wr2] concat, tf32 bits
__device__ int   g_deg [NN];           // zero at start of every call
__device__ int   g_ex  [NN];
__device__ int   g_off [NN + 1];
__device__ int   g_cur [NN];
__device__ int   g_csrc[EEv];
__device__ int   g_bsum[64];

// ---------------- mma helpers ----------------
__device__ __forceinline__ uint32_t f2tf(float f) {
    uint32_t u;
    asm("cvt.rna.tf32.f32 %0, %1;" : "=r"(u) : "f"(f));
    return u;
}

// tf32 m16n8k8 (kept for gemm2)
__device__ __forceinline__ void mma8(float* c, const uint32_t* a, const uint32_t* b) {
    asm volatile(
        "mma.sync.aligned.m16n8k8.row.col.f32.tf32.tf32.f32 "
        "{%0,%1,%2,%3},{%4,%5,%6,%7},{%8,%9},{%0,%1,%2,%3};\n"
        : "+f"(c[0]), "+f"(c[1]), "+f"(c[2]), "+f"(c[3])
        : "r"(a[0]), "r"(a[1]), "r"(a[2]), "r"(a[3]), "r"(b[0]), "r"(b[1]));
}

// fp16 m16n8k16, fp32 accumulate (gemm1)
__device__ __forceinline__ void mma16(float* c, const uint32_t* a, const uint32_t* b) {
    asm volatile(
        "mma.sync.aligned.m16n8k16.row.col.f32.f16.f16.f32 "
        "{%0,%1,%2,%3},{%4,%5,%6,%7},{%8,%9},{%0,%1,%2,%3};\n"
        : "+f"(c[0]), "+f"(c[1]), "+f"(c[2]), "+f"(c[3])
        : "r"(a[0]), "r"(a[1]), "r"(a[2]), "r"(a[3]), "r"(b[0]), "r"(b[1]));
}

__device__ __forceinline__ void ldm4(uint32_t* r, uint32_t addr) {
    asm volatile("ldmatrix.sync.aligned.m8n8.x4.shared.b16 {%0,%1,%2,%3}, [%4];"
        : "=r"(r[0]), "=r"(r[1]), "=r"(r[2]), "=r"(r[3]) : "r"(addr));
}

__device__ __forceinline__ void cp16(uint32_t dst, const void* src, int sz) {
    asm volatile("cp.async.cg.shared.global [%0], [%1], 16, %2;\n"
                 :: "r"(dst), "l"(src), "r"(sz));
}
__device__ __forceinline__ void cpcommit() { asm volatile("cp.async.commit_group;\n" ::: "memory"); }
__device__ __forceinline__ void cpwait0()  { asm volatile("cp.async.wait_group 0;\n" ::: "memory"); }
__device__ __forceinline__ void cpwait1()  { asm volatile("cp.async.wait_group 1;\n" ::: "memory"); }

__device__ __forceinline__ uint32_t smem_u32(const void* p) {
    uint32_t a;
    asm("{ .reg .u64 t; cvta.to.shared.u64 t, %1; cvt.u32.u64 %0, t; }" : "=r"(a) : "l"(p));
    return a;
}

// ---------------- weight preprocessing (main stream, feeds gemm1/gemm2) -----
__global__ void k_wconv(const float* __restrict__ Wl1, const float* __restrict__ Wr1,
                        const float* __restrict__ Wl2, const float* __restrict__ Wr2) {
    int e = blockIdx.x * 256 + threadIdx.x;
    if (e < 2 * HC * HC) {      // transpose+convert layer-1 weights: g_w1h[z][n][k]
        int z = e >> 16, idx = e & 65535;
        int n = idx >> 8, k = idx & 255;
        const float* Wz = z ? Wr1 : Wl1;
        g_w1h[z * 65536 + n * 256 + k] = __float2half(Wz[k * 256 + n]);
    }
    if (e < HC * OUTD) {
        int r = e >> 4, c = e & 15;
        g_w2t[r * 32 + c]      = __uint_as_float(f2tf(Wl2[e]));
        g_w2t[r * 32 + 16 + c] = __uint_as_float(f2tf(Wr2[e]));
    }
}

// ---------------- CSR build (side stream) -----------------------------------
__global__ void k_hist(const int* __restrict__ ei) {
    int e = blockIdx.x * 256 + threadIdx.x;
    if (e >= EEv) return;
    int d = (e < EI) ? ei[EI + e] : (e - EI);
    atomicAdd(&g_deg[d], 1);
}

__global__ void k_scan1() {
    int i = blockIdx.x * 1024 + threadIdx.x;
    int v = (i < NN) ? g_deg[i] : 0;
    int x = v;
    #pragma unroll
    for (int o = 1; o < 32; o <<= 1) {
        int y = __shfl_up_sync(0xffffffffu, x, o);
        if ((threadIdx.x & 31) >= o) x += y;
    }
    __shared__ int ws[32];
    if ((threadIdx.x & 31) == 31) ws[threadIdx.x >> 5] = x;
    __syncthreads();
    if (threadIdx.x < 32) {
        int s = ws[threadIdx.x];
        #pragma unroll
        for (int o = 1; o < 32; o <<= 1) {
            int y = __shfl_up_sync(0xffffffffu, s, o);
            if (threadIdx.x >= (unsigned)o) s += y;
        }
        ws[threadIdx.x] = s;
    }
    __syncthreads();
    int incl = x + ((threadIdx.x >= 32) ? ws[(threadIdx.x >> 5) - 1] : 0);
    if (i < NN) g_ex[i] = incl - v;
    if (threadIdx.x == 1023) g_bsum[blockIdx.x] = incl;
}

__global__ void k_off() {
    __shared__ int s_pre[2];
    int t = threadIdx.x;
    int gb = blockIdx.x >> 2;
    if (t < 64) {
        int v = (t < gb && t < NB1) ? g_bsum[t] : 0;
        #pragma unroll
        for (int o = 16; o >= 1; o >>= 1) v += __shfl_xor_sync(0xffffffffu, v, o);
        if ((t & 31) == 0) s_pre[t >> 5] = v;
    }
    __syncthreads();
    int pre = s_pre[0] + s_pre[1];
    int i = blockIdx.x * 256 + t;
    if (i < NN) {
        int o = g_ex[i] + pre;
        g_off[i] = o;
        g_cur[i] = o;
    }
    if (i == 0) g_off[NN] = EEv;
}

__global__ void k_scatter(const int* __restrict__ ei) {
    int e = blockIdx.x * 256 + threadIdx.x;
    if (e < NN) g_deg[e] = 0;
    if (e >= EEv) return;
    int s = (e < EI) ? ei[e]      : (e - EI);
    int d = (e < EI) ? ei[EI + e] : (e - EI);
    int p = atomicAdd(&g_cur[d], 1);
    g_csrc[p] = s;
}

// ---------------- layer-1 GEMM: fp16 HMMA m16n8k16 + ldmatrix ---------------
// BM=128, BN=128, BK=32; 256 threads, 8 warps (4m x 2n), warp tile 32x64.
// 3-stage ring, ONE __syncthreads per iteration (R4-style rotation):
// after the barrier of iter i, buffer (i+2)%3 == (i-1)%3 is free -> fill it.
#define AH 40
#define BH 40
#define ASTG (128 * AH)     // fp16 per A stage
#define BSTG (128 * BH)     // fp16 per B stage
__global__ __launch_bounds__(256, 2) void k_gemm1h(
    const float* __restrict__ X,
    const float* __restrict__ b0, const float* __restrict__ b1)
{
    extern __shared__ __half smh[];
    __half* As = smh;                // [3][ASTG]
    __half* Bs = smh + 3 * ASTG;     // [3][BSTG]

    const __half* W   = g_w1h + (size_t)blockIdx.z * 65536;
    const float* bias = blockIdx.z ? b1 : b0;

    int m0 = blockIdx.x * 128;
    int n0 = blockIdx.y * 128;
    int t = threadIdx.x;
    int warp = t >> 5, lane = t & 31;
    int wm = warp & 3, wn = warp >> 2;
    int r = lane >> 2, cq = lane & 3;

    uint32_t aS = smem_u32(As);
    uint32_t bS = smem_u32(Bs);

    int arow_lm = lane & 15;
    int akoff   = (lane >> 4) * 8;
    int nrow_lm = (lane & 7) + ((lane >> 4) << 3);
    int bkoff   = lane & 8;

    float c[2][8][4];
    #pragma unroll
    for (int mt = 0; mt < 2; mt++)
        #pragma unroll
        for (int nt = 0; nt < 8; nt++)
            #pragma unroll
            for (int q = 0; q < 4; q++) c[mt][nt][q] = 0.f;

    int arow = t >> 1, ahalf = t & 1;
    const float* aptr = X + (size_t)(m0 + arow) * 256 + ahalf * 16;
    bool aok = (m0 + arow) < NN;
    float4 va[4];
    auto ldgA = [&](int kb) {
        #pragma unroll
        for (int j = 0; j < 4; j++)
            va[j] = aok ? *(const float4*)(aptr + kb + j * 4)
                        : make_float4(0.f, 0.f, 0.f, 0.f);
    };
    auto stsA = [&](int s) {
        uint32_t h[8];
        #pragma unroll
        for (int j = 0; j < 4; j++) {
            __half2 lo = __floats2half2_rn(va[j].x, va[j].y);
            __half2 hi = __floats2half2_rn(va[j].z, va[j].w);
            h[2 * j]     = *(uint32_t*)&lo;
            h[2 * j + 1] = *(uint32_t*)&hi;
        }
        uint32_t dst = aS + (uint32_t)(s * ASTG + arow * AH + ahalf * 16) * 2u;
        asm volatile("st.shared.v4.b32 [%0], {%1,%2,%3,%4};"
                     :: "r"(dst), "r"(h[0]), "r"(h[1]), "r"(h[2]), "r"(h[3]) : "memory");
        asm volatile("st.shared.v4.b32 [%0], {%1,%2,%3,%4};"
                     :: "r"(dst + 16), "r"(h[4]), "r"(h[5]), "r"(h[6]), "r"(h[7]) : "memory");
    };
    auto cpB = [&](int s, int kb) {
        #pragma unroll
        for (int j = 0; j < 2; j++) {
            int g   = t + j * 256;
            int row = g >> 2, q = g & 3;
            uint32_t dst = bS + (uint32_t)(s * BSTG + row * BH + q * 8) * 2u;
            cp16(dst, W + (size_t)(n0 + row) * 256 + kb + q * 8, 16);
        }
    };

    // prologue: stages 0 and 1 filled; A data for stage 2 staged in regs
    ldgA(0);  stsA(0);
    cpB(0, 0);  cpcommit();
    ldgA(32); stsA(1);
    cpB(1, 32); cpcommit();
    ldgA(64);

    #pragma unroll 1
    for (int i = 0; i < 8; i++) {
        int s = i % 3;
        if (i == 7) cpwait0(); else cpwait1();
        __syncthreads();
        if (i + 2 < 8) {
            int s2 = (i + 2) % 3;
            stsA(s2);
            cpB(s2, (i + 2) * 32); cpcommit();
            if (i + 3 < 8) ldgA((i + 3) * 32);
        }

        uint32_t aBase = aS + (uint32_t)(s * ASTG) * 2u;
        uint32_t bBase = bS + (uint32_t)(s * BSTG) * 2u;
        #pragma unroll
        for (int ks = 0; ks < 2; ks++) {
            int k = ks * 16;
            uint32_t a[2][4], b[8][2];
            #pragma unroll
            for (int mt = 0; mt < 2; mt++) {
                uint32_t ad = aBase +
                    (uint32_t)((wm * 32 + mt * 16 + arow_lm) * AH + k + akoff) * 2u;
                ldm4(a[mt], ad);
            }
            #pragma unroll
            for (int ntp = 0; ntp < 4; ntp++) {
                uint32_t bd = bBase +
                    (uint32_t)((wn * 64 + ntp * 16 + nrow_lm) * BH + k + bkoff) * 2u;
                ldm4(&b[2 * ntp][0], bd);
            }
            #pragma unroll
            for (int mt = 0; mt < 2; mt++)
                #pragma unroll
                for (int nt = 0; nt < 8; nt++)
                    mma16(c[mt][nt], a[mt], b[nt]);
        }
    }

    // epilogue: + bias; xl -> fp16, xr -> fp32
    if (blockIdx.z == 0) {
        #pragma unroll
        for (int mt = 0; mt < 2; mt++) {
            #pragma unroll
            for (int nt = 0; nt < 8; nt++) {
                int gr = m0 + wm * 32 + mt * 16 + r;
                int gc = n0 + wn * 64 + nt * 8 + cq * 2;
                float bv0 = bias[gc], bv1 = bias[gc + 1];
                if (gr < NN)
                    g_xl1h[(size_t)gr * 128 + (gc >> 1)] =
                        __floats2half2_rn(c[mt][nt][0] + bv0, c[mt][nt][1] + bv1);
                if (gr + 8 < NN)
                    g_xl1h[(size_t)(gr + 8) * 128 + (gc >> 1)] =
                        __floats2half2_rn(c[mt][nt][2] + bv0, c[mt][nt][3] + bv1);
            }
        }
    } else {
        #pragma unroll
        for (int mt = 0; mt < 2; mt++) {
            #pragma unroll
            for (int nt = 0; nt < 8; nt++) {
                int gr = m0 + wm * 32 + mt * 16 + r;
                int gc = n0 + wn * 64 + nt * 8 + cq * 2;
                float bv0 = bias[gc], bv1 = bias[gc + 1];
                if (gr < NN) {
                    float2 v; v.x = c[mt][nt][0] + bv0; v.y = c[mt][nt][1] + bv1;
                    *(float2*)&g_xr1[(size_t)gr * HC + gc] = v;
                }
                if (gr + 8 < NN) {
                    float2 v; v.x = c[mt][nt][2] + bv0; v.y = c[mt][nt][3] + bv1;
                    *(float2*)&g_xr1[(size_t)(gr + 8) * HC + gc] = v;
                }
            }
        }
    }
}

// ---------------- layer-1 attention: 2-edge-paired online softmax ------------
__global__ __launch_bounds__(256) void k_agg1(const float* __restrict__ att,
                                              const float* __restrict__ b1)
{
    int gw   = (blockIdx.x * 256 + threadIdx.x) >> 5;
    int lane = threadIdx.x & 31;
    if (gw >= NN) return;
    int c0 = lane * 8;
    size_t lo = (size_t)lane * 4;

    const float4* xrp = (const float4*)&g_xr1[(size_t)gw * HC + c0];
    float4 xr0 = xrp[0], xr1 = xrp[1];
    const float4* ap = (const float4*)&att[c0];
    float4 at0 = ap[0], at1 = ap[1];

    float acc[8];
    #pragma unroll
    for (int q = 0; q < 8; q++) acc[q] = 0.f;
    float den = 0.f, mx = -1e30f;

    int off = g_off[gw], dg = g_off[gw + 1] - off;

    auto score = [&](const uint4& raw, float* f) -> float {
        const __half2* hp = (const __half2*)&raw;
        float2 a0 = __half22float2(hp[0]);
        float2 a1 = __half22float2(hp[1]);
        float2 a2 = __half22float2(hp[2]);
        float2 a3 = __half22float2(hp[3]);
        f[0] = a0.x; f[1] = a0.y; f[2] = a1.x; f[3] = a1.y;
        f[4] = a2.x; f[5] = a2.y; f[6] = a3.x; f[7] = a3.y;
        float m, l, p;
        m = a0.x + xr0.x; l = (m > 0.f) ? m : NEG * m; p  = l * at0.x;
        m = a0.y + xr0.y; l = (m > 0.f) ? m : NEG * m; p += l * at0.y;
        m = a1.x + xr0.z; l = (m > 0.f) ? m : NEG * m; p += l * at0.z;
        m = a1.y + xr0.w; l = (m > 0.f) ? m : NEG * m; p += l * at0.w;
        m = a2.x + xr1.x; l = (m > 0.f) ? m : NEG * m; p += l * at1.x;
        m = a2.y + xr1.y; l = (m > 0.f) ? m : NEG * m; p += l * at1.y;
        m = a3.x + xr1.z; l = (m > 0.f) ? m : NEG * m; p += l * at1.z;
        m = a3.y + xr1.w; l = (m > 0.f) ? m : NEG * m; p += l * at1.w;
        return p;
    };

    // prefetch edges 0,1
    int sA = g_csrc[off];
    int sB = g_csrc[off + ((dg > 1) ? 1 : 0)];
    uint4 rawA = *(const uint4*)&g_xl1h[(size_t)sA * 128 + lo];
    uint4 rawB = *(const uint4*)&g_xl1h[(size_t)sB * 128 + lo];

    int i = 0;
    for (; i + 1 < dg; i += 2) {
        uint4 c0v = rawA, c1v = rawB;
        int n0i = min(i + 2, dg - 1);
        int n1i = min(i + 3, dg - 1);
        int sn0 = g_csrc[off + n0i];
        int sn1 = g_csrc[off + n1i];
        rawA = *(const uint4*)&g_xl1h[(size_t)sn0 * 128 + lo];
        rawB = *(const uint4*)&g_xl1h[(size_t)sn1 * 128 + lo];

        float f0[8], f1[8];
        float p0 = score(c0v, f0);
        float p1 = score(c1v, f1);
        p0 += __shfl_xor_sync(0xffffffffu, p0, 1);
        p1 += __shfl_xor_sync(0xffffffffu, p1, 1);
        p0 += __shfl_xor_sync(0xffffffffu, p0, 2);
        p1 += __shfl_xor_sync(0xffffffffu, p1, 2);
        p0 += __shfl_xor_sync(0xffffffffu, p0, 4);
        p1 += __shfl_xor_sync(0xffffffffu, p1, 4);

        float mn   = fmaxf(mx, fmaxf(p0, p1));
        float corr = __expf(mx - mn);
        float w0   = __expf(p0 - mn);
        float w1   = __expf(p1 - mn);
        mx  = mn;
        den = den * corr + w0 + w1;
        #pragma unroll
        for (int q = 0; q < 8; q++)
            acc[q] = acc[q] * corr + w0 * f0[q] + w1 * f1[q];
    }
    if (i < dg) {   // odd remainder: edge dg-1 is in rawA
        float f0[8];
        float p0 = score(rawA, f0);
        p0 += __shfl_xor_sync(0xffffffffu, p0, 1);
        p0 += __shfl_xor_sync(0xffffffffu, p0, 2);
        p0 += __shfl_xor_sync(0xffffffffu, p0, 4);
        float mn   = fmaxf(mx, p0);
        float corr = __expf(mx - mn);
        float w0   = __expf(p0 - mn);
        mx  = mn;
        den = den * corr + w0;
        #pragma unroll
        for (int q = 0; q < 8; q++)
            acc[q] = acc[q] * corr + w0 * f0[q];
    }

    float inv = 1.f / (den + 1e-16f);
    float4 o0, o1;
    o0.x = __uint_as_float(f2tf(tanhf(acc[0] * inv + b1[c0 + 0])));
    o0.y = __uint_as_float(f2tf(tanhf(acc[1] * inv + b1[c0 + 1])));
    o0.z = __uint_as_float(f2tf(tanhf(acc[2] * inv + b1[c0 + 2])));
    o0.w = __uint_as_float(f2tf(tanhf(acc[3] * inv + b1[c0 + 3])));
    o1.x = __uint_as_float(f2tf(tanhf(acc[4] * inv + b1[c0 + 4])));
    o1.y = __uint_as_float(f2tf(tanhf(acc[5] * inv + b1[c0 + 5])));
    o1.z = __uint_as_float(f2tf(tanhf(acc[6] * inv + b1[c0 + 6])));
    o1.w = __uint_as_float(f2tf(tanhf(acc[7] * inv + b1[c0 + 7])));
    float4* hpo = (float4*)&g_h[(size_t)gw * HC + c0];
    hpo[0] = o0; hpo[1] = o1;
}

// ---------------- layer-2 GEMM (tf32 HMMA): [xl2|xr2] = h @ [Wl2|Wr2] + b ----
#define AP2 36
#define BP2 40
__global__ __launch_bounds__(256) void k_gemm2(
    const float* __restrict__ bl2, const float* __restrict__ br2)
{
    extern __shared__ float smemf[];
    float* As = smemf;                  // [2][128*AP2]
    float* Bs = smemf + 2 * 128 * AP2;  // [256*BP2]
    float* bs = Bs + 256 * BP2;         // [32]

    int m0 = blockIdx.x * 128;
    int t = threadIdx.x;
    int warp = t >> 5, lane = t & 31;
    int ar = lane >> 2, ac = lane & 3;

    #pragma unroll
    for (int i = 0; i < 8; i++) {
        int lin = t + i * 256;
        int r   = lin >> 3;
        int c4  = (lin & 7) * 4;
        float4 v = *(const float4*)&g_w2t[r * 32 + c4];
        float* d = Bs + r * BP2 + c4;
        d[0] = v.x; d[1] = v.y; d[2] = v.z; d[3] = v.w;
    }
    if (t < 32) bs[t] = (t < 16) ? bl2[t] : br2[t - 16];

    uint32_t aS = (uint32_t)__cvta_generic_to_shared(As);

    float c[4][4];
    #pragma unroll
    for (int nt = 0; nt < 4; nt++)
        #pragma unroll
        for (int q = 0; q < 4; q++) c[nt][q] = 0.f;

    auto load_stage = [&](int s, int kb) {
        uint32_t ab = aS + (uint32_t)(s * 128 * AP2) * 4u;
        #pragma unroll
        for (int i = 0; i < 4; i++) {
            int r  = (t >> 3) + i * 32;
            int c4 = (t & 7) * 4;
            int gr = m0 + r;
            const float* src = g_h + (size_t)gr * 256 + kb + c4;
            cp16(ab + (uint32_t)(r * AP2 + c4) * 4u, src, (gr < NN) ? 16 : 0);
        }
    };

    load_stage(0, 0);
    cpcommit();

    for (int i = 0; i < 8; i++) {
        cpwait0();
        __syncthreads();
        if (i + 1 < 8) { load_stage((i + 1) & 1, (i + 1) * 32); cpcommit(); }

        const uint32_t* Ac = (const uint32_t*)(As + (i & 1) * 128 * AP2);
        const uint32_t* Bu = (const uint32_t*)Bs;
        int kb = i * 32;
        #pragma unroll
        for (int ks = 0; ks < 4; ks++) {
            int k = ks * 8;
            uint32_t a[4], b[4][2];
            int m = warp * 16;
            a[0] = Ac[(m + ar)     * AP2 + k + ac];
            a[1] = Ac[(m + ar + 8) * AP2 + k + ac];
            a[2] = Ac[(m + ar)     * AP2 + k + ac + 4];
            a[3] = Ac[(m + ar + 8) * AP2 + k + ac + 4];
            #pragma unroll
            for (int nt = 0; nt < 4; nt++) {
                int n = nt * 8 + ar;
                b[nt][0] = Bu[(kb + k + ac)     * BP2 + n];
                b[nt][1] = Bu[(kb + k + ac + 4) * BP2 + n];
            }
            #pragma unroll
            for (int nt = 0; nt < 4; nt++)
                mma8(c[nt], a, b[nt]);
        }
        __syncthreads();
    }

    #pragma unroll
    for (int nt = 0; nt < 4; nt++) {
        int gr = m0 + warp * 16 + ar;
        int gc = nt * 8 + ac * 2;
        float bv0 = bs[gc], bv1 = bs[gc + 1];
        float* base = (gc < 16) ? g_xl2 : g_xr2;
        int col = (gc < 16) ? gc : gc - 16;
        if (gr < NN) {
            float2 v; v.x = c[nt][0] + bv0; v.y = c[nt][1] + bv1;
            *(float2*)&base[(size_t)gr * OUTD + col] = v;
        }
        if (gr + 8 < NN) {
            float2 v; v.x = c[nt][2] + bv0; v.y = c[nt][3] + bv1;
            *(float2*)&base[(size_t)(gr + 8) * OUTD + col] = v;
        }
    }
}

// ---------------- layer-2 aggregation (2 nodes/warp, 2-edge-paired) ---------
__global__ __launch_bounds__(256) void k_agg2(const float* __restrict__ att2,
                                              const float* __restrict__ b2,
                                              float* __restrict__ out,
                                              int out_size)
{
    int warpg = (blockIdx.x * 256 + threadIdx.x) >> 5;
    int lane  = threadIdx.x & 31;
    int half  = lane >> 4;
    int j     = lane & 15;
    int node  = warpg * 2 + half;
    bool ok   = node < NN;
    if (warpg * 2 >= NN) return;

    float xr = ok ? g_xr2[(size_t)node * OUTD + j] : 0.f;
    float at = att2[j];
    float acc = 0.f, den = 0.f, mx = -1e30f;

    int off = ok ? g_off[node] : 0;
    int dg  = ok ? (g_off[node + 1] - off) : 0;
    int dmax = __reduce_max_sync(0xffffffffu, dg);

    for (int i = 0; i < dmax; i += 2) {
        int i0 = (dg > 0) ? min(i,     dg - 1) : 0;
        int i1 = (dg > 0) ? min(i + 1, dg - 1) : 0;
        int s0 = g_csrc[off + i0];
        int s1 = g_csrc[off + i1];
        float v0 = g_xl2[(size_t)s0 * OUTD + j];
        float v1 = g_xl2[(size_t)s1 * OUTD + j];
        float m0v = v0 + xr, m1v = v1 + xr;
        float l0 = (m0v > 0.f) ? m0v : NEG * m0v;
        float l1 = (m1v > 0.f) ? m1v : NEG * m1v;
        float p0 = l0 * at, p1 = l1 * at;
        p0 += __shfl_xor_sync(0xffffffffu, p0, 1);
        p1 += __shfl_xor_sync(0xffffffffu, p1, 1);
        p0 += __shfl_xor_sync(0xffffffffu, p0, 2);
        p1 += __shfl_xor_sync(0xffffffffu, p1, 2);
        p0 += __shfl_xor_sync(0xffffffffu, p0, 4);
        p1 += __shfl_xor_sync(0xffffffffu, p1, 4);
        p0 += __shfl_xor_sync(0xffffffffu, p0, 8);
        p1 += __shfl_xor_sync(0xffffffffu, p1, 8);
        if (i     >= dg) p0 = -1e30f;
        if (i + 1 >= dg) p1 = -1e30f;
        float mn   = fmaxf(mx, fmaxf(p0, p1));
        float corr = __expf(mx - mn);
        float w0   = __expf(p0 - mn);
        float w1   = __expf(p1 - mn);
        mx  = mn;
        den = den * corr + w0 + w1;
        acc = acc * corr + w0 * v0 + w1 * v1;
    }
    float o = acc / (den + 1e-16f) + b2[j];

    float mo = o;
    mo = fmaxf(mo, __shfl_xor_sync(0xffffffffu, mo, 1));
    mo = fmaxf(mo, __shfl_xor_sync(0xffffffffu, mo, 2));
    mo = fmaxf(mo, __shfl_xor_sync(0xffffffffu, mo, 4));
    mo = fmaxf(mo, __shfl_xor_sync(0xffffffffu, mo, 8));
    float ex = __expf(o - mo);
    float se = ex;
    se += __shfl_xor_sync(0xffffffffu, se, 1);
    se += __shfl_xor_sync(0xffffffffu, se, 2);
    se += __shfl_xor_sync(0xffffffffu, se, 4);
    se += __shfl_xor_sync(0xffffffffu, se, 8);
    float ls = o - mo - logf(se);

    if (ok) {
        int i0 = node * OUTD + j;
        if (i0 < out_size) out[i0] = o;
        int i1 = NN * OUTD + node * OUTD + j;
        if (i1 < out_size) out[i1] = ls;
    }
}

// ---------------- launch: fork CSR build onto a side stream ------------------
extern "C" void kernel_launch(void* const* d_in, const int* in_sizes, int n_in,
                              void* d_out, int out_size)
{
    const float* x     = (const float*)d_in[0];
    const int*   ei    = (const int*)  d_in[1];
    const float* Wl1   = (const float*)d_in[2];
    const float* bl1   = (const float*)d_in[3];
    const float* Wr1   = (const float*)d_in[4];
    const float* br1   = (const float*)d_in[5];
    const float* att1  = (const float*)d_in[6];
    const float* bias1 = (const float*)d_in[7];
    const float* Wl2   = (const float*)d_in[8];
    const float* bl2   = (const float*)d_in[9];
    const float* Wr2   = (const float*)d_in[10];
    const float* br2   = (const float*)d_in[11];
    const float* att2  = (const float*)d_in[12];
    const float* bias2 = (const float*)d_in[13];
    float* out = (float*)d_out;

    const int smem1 = 3 * (ASTG + BSTG) * 2;                 // 61440 B
    const int smem2 = (2 * 128 * AP2 + 256 * BP2 + 32) * 4;  // 77952 B
    cudaFuncSetAttribute(k_gemm1h, cudaFuncAttributeMaxDynamicSharedMemorySize, smem1);
    cudaFuncSetAttribute(k_gemm2, cudaFuncAttributeMaxDynamicSharedMemorySize, smem2);

    // side stream + events (host objects; created per call, intentionally not
    // destroyed — destroying a stream that holds capture dependencies can
    // abort graph capture. kernel_launch is invoked only a handful of times.)
    cudaStream_t s2;
    cudaStreamCreate(&s2);
    cudaEvent_t eFork, eJoin;
    cudaEventCreateWithFlags(&eFork, cudaEventDisableTiming);
    cudaEventCreateWithFlags(&eJoin, cudaEventDisableTiming);

    // fork: CSR build on side stream, GEMM path on main stream
    cudaEventRecord(eFork, 0);
    cudaStreamWaitEvent(s2, eFork, 0);

    k_hist   <<<(EEv + 255) / 256, 256, 0, s2>>>(ei);
    k_scan1  <<<NB1, 1024, 0, s2>>>();
    k_off    <<<(NN + 255) / 256, 256, 0, s2>>>();
    k_scatter<<<(EEv + 255) / 256, 256, 0, s2>>>(ei);
    cudaEventRecord(eJoin, s2);

    k_wconv  <<<512, 256>>>(Wl1, Wr1, Wl2, Wr2);
    dim3 g1((NN + 127) / 128, 2, 2);
    k_gemm1h <<<g1, 256, smem1>>>(x, bl1, br1);

    // join: agg1 needs both xl1/xr1 (main) and CSR (side)
    cudaStreamWaitEvent(0, eJoin, 0);
    k_agg1   <<<(NN * 32 + 255) / 256, 256>>>(att1, bias1);
    k_gemm2  <<<(NN + 127) / 128, 256, smem2>>>(bl2, br2);
    k_agg2   <<<((NN / 2) * 32 + 255) / 256, 256>>>(att2, bias2, out, out_size);
}